// round 16
// baseline (speedup 1.0000x reference)
#include <cuda_runtime.h>
#include <math.h>

#define NB 8192
#define NV 101
#define NT 30
#define NC 4
#define ND 64
#define NH 128
#define NVP 112     // padded row count (zeroed pad rows 101..111)
#define DSTR 104    // dyn row stride (104%32=8 -> conflict-free act loads)
#define HSTR 68     // sh/swk row stride (68%32=4 -> conflict-free act loads)

typedef unsigned long long u64;

// Scratch (static device arrays: allowed; no cudaMalloc anywhere)
__device__ float g_h[(size_t)NB * NV * ND];   // final hidden states (B, V*64)
__device__ float g_y[(size_t)NB * NH];        // relu(flat @ Wf1 + bf1)

// ---------------- SMEM layout (floats) ----------------
#define OFF_W2   0                     // 64*64    = 4096
#define OFF_WZ   4096                  // 132*64   = 8448
#define OFF_WR   12544                 // 8448
#define OFF_WW   20992                 // 8448
#define OFF_W1   29440                 // 4*64     = 256
#define OFF_H    29696                 // 112*68   = 7616
#define OFF_WK   37312                 // 7616
#define OFF_DYN  44928                 // 112*104  = 11648
#define OFF_XT   56576                 // 112*4    = 448
#define OFF_AGG  57024                 // 448
#define OFF_B1   57472
#define OFF_B2   57536
#define OFF_BZ   57600
#define OFF_BR   57664
#define OFF_BW   57728
#define SMEM_FLOATS 57792
#define SMEM_BYTES (SMEM_FLOATS * 4)   // 231,168 B <= 232,448 cap

// ---- fast activations (MUFU ex2/rcp; validated: rel_err 8.3e-8) ----
__device__ __forceinline__ float ex2f(float x) {
    float y; asm("ex2.approx.f32 %0, %1;" : "=f"(y) : "f"(x)); return y;
}
__device__ __forceinline__ float rcpf(float x) {
    float y; asm("rcp.approx.f32 %0, %1;" : "=f"(y) : "f"(x)); return y;
}
#define LOG2E_F 1.4426950408889634f
__device__ __forceinline__ float sigm(float v) {
    return rcpf(1.0f + ex2f(-v * LOG2E_F));
}
__device__ __forceinline__ float tanh_fast(float v) {
    return 1.0f - 2.0f * rcpf(1.0f + ex2f(v * (2.0f * LOG2E_F)));
}

// ---- packed f32x2 primitives (exact fp32 RN, 2 FMAs/instr) ----
__device__ __forceinline__ u64 pk2(float lo, float hi) {
    u64 r; asm("mov.b64 %0, {%1, %2};" : "=l"(r) : "f"(lo), "f"(hi)); return r;
}
__device__ __forceinline__ void upk2(float& lo, float& hi, u64 v) {
    asm("mov.b64 {%0, %1}, %2;" : "=f"(lo), "=f"(hi) : "l"(v));
}
__device__ __forceinline__ u64 ffma2(u64 a, u64 b, u64 c) {
    u64 d; asm("fma.rn.f32x2 %0, %1, %2, %3;" : "=l"(d) : "l"(a), "l"(b), "l"(c));
    return d;
}

// Two-panel tile: acc[4 rows][4 u64] covers cols {c0..c0+3} (acc[r][0..1])
// and {c0+32..c0+35} (acc[r][2..3]). Rows: rowbase + r*4 (r=0..3).
// Weight LDS.128: 8 lanes x 16B contiguous 128B + broadcast -> 1 wavefront.
// Act LDS.128: 4 lr-consecutive rows, strides chosen conflict-free.
__device__ __forceinline__ void gemmT(u64 acc[4][4],
    const float* __restrict__ act, int astride, int rowbase,
    const float* __restrict__ W, int wstride, int K, int c0)
{
    const float* wa = W + c0;
    const float* wb = W + c0 + 32;
#pragma unroll 2
    for (int k = 0; k < K; k += 4) {
        float4 av[4];
#pragma unroll
        for (int r = 0; r < 4; ++r)
            av[r] = *reinterpret_cast<const float4*>(act + (rowbase + r * 4) * astride + k);
#pragma unroll
        for (int kk = 0; kk < 4; ++kk) {
            ulonglong2 wva = *reinterpret_cast<const ulonglong2*>(wa + (k + kk) * wstride);
            ulonglong2 wvb = *reinterpret_cast<const ulonglong2*>(wb + (k + kk) * wstride);
#pragma unroll
            for (int r = 0; r < 4; ++r) {
                float a = reinterpret_cast<const float*>(&av[r])[kk];
                u64 ad = pk2(a, a);
                acc[r][0] = ffma2(ad, wva.x, acc[r][0]);
                acc[r][1] = ffma2(ad, wva.y, acc[r][1]);
                acc[r][2] = ffma2(ad, wvb.x, acc[r][2]);
                acc[r][3] = ffma2(ad, wvb.y, acc[r][3]);
            }
        }
    }
}

// fused 3-matrix version: one act pass feeds z, r, w accumulators.
__device__ __forceinline__ void gemmT3(u64 aZ[4][4], u64 aR[4][4], u64 aW[4][4],
    const float* __restrict__ act, int astride, int rowbase,
    const float* __restrict__ WZp, const float* __restrict__ WRp,
    const float* __restrict__ WWp, int K, int c0)
{
    const float* wza = WZp + c0; const float* wzb = WZp + c0 + 32;
    const float* wra = WRp + c0; const float* wrb = WRp + c0 + 32;
    const float* wwa = WWp + c0; const float* wwb = WWp + c0 + 32;
#pragma unroll 1
    for (int k = 0; k < K; k += 4) {
        float4 av[4];
#pragma unroll
        for (int r = 0; r < 4; ++r)
            av[r] = *reinterpret_cast<const float4*>(act + (rowbase + r * 4) * astride + k);
#pragma unroll
        for (int kk = 0; kk < 4; ++kk) {
            ulonglong2 vza = *reinterpret_cast<const ulonglong2*>(wza + (k + kk) * 64);
            ulonglong2 vzb = *reinterpret_cast<const ulonglong2*>(wzb + (k + kk) * 64);
            ulonglong2 vra = *reinterpret_cast<const ulonglong2*>(wra + (k + kk) * 64);
            ulonglong2 vrb = *reinterpret_cast<const ulonglong2*>(wrb + (k + kk) * 64);
            ulonglong2 vwa = *reinterpret_cast<const ulonglong2*>(wwa + (k + kk) * 64);
            ulonglong2 vwb = *reinterpret_cast<const ulonglong2*>(wwb + (k + kk) * 64);
#pragma unroll
            for (int r = 0; r < 4; ++r) {
                float a = reinterpret_cast<const float*>(&av[r])[kk];
                u64 ad = pk2(a, a);
                aZ[r][0] = ffma2(ad, vza.x, aZ[r][0]);
                aZ[r][1] = ffma2(ad, vza.y, aZ[r][1]);
                aZ[r][2] = ffma2(ad, vzb.x, aZ[r][2]);
                aZ[r][3] = ffma2(ad, vzb.y, aZ[r][3]);
                aR[r][0] = ffma2(ad, vra.x, aR[r][0]);
                aR[r][1] = ffma2(ad, vra.y, aR[r][1]);
                aR[r][2] = ffma2(ad, vrb.x, aR[r][2]);
                aR[r][3] = ffma2(ad, vrb.y, aR[r][3]);
                aW[r][0] = ffma2(ad, vwa.x, aW[r][0]);
                aW[r][1] = ffma2(ad, vwa.y, aW[r][1]);
                aW[r][2] = ffma2(ad, vwb.x, aW[r][2]);
                aW[r][3] = ffma2(ad, vwb.y, aW[r][3]);
            }
        }
    }
}

// fused 2-matrix version (z, r over the h-segment)
__device__ __forceinline__ void gemmT2(u64 aZ[4][4], u64 aR[4][4],
    const float* __restrict__ act, int astride, int rowbase,
    const float* __restrict__ WZp, const float* __restrict__ WRp, int K, int c0)
{
    const float* wza = WZp + c0; const float* wzb = WZp + c0 + 32;
    const float* wra = WRp + c0; const float* wrb = WRp + c0 + 32;
#pragma unroll 1
    for (int k = 0; k < K; k += 4) {
        float4 av[4];
#pragma unroll
        for (int r = 0; r < 4; ++r)
            av[r] = *reinterpret_cast<const float4*>(act + (rowbase + r * 4) * astride + k);
#pragma unroll
        for (int kk = 0; kk < 4; ++kk) {
            ulonglong2 vza = *reinterpret_cast<const ulonglong2*>(wza + (k + kk) * 64);
            ulonglong2 vzb = *reinterpret_cast<const ulonglong2*>(wzb + (k + kk) * 64);
            ulonglong2 vra = *reinterpret_cast<const ulonglong2*>(wra + (k + kk) * 64);
            ulonglong2 vrb = *reinterpret_cast<const ulonglong2*>(wrb + (k + kk) * 64);
#pragma unroll
            for (int r = 0; r < 4; ++r) {
                float a = reinterpret_cast<const float*>(&av[r])[kk];
                u64 ad = pk2(a, a);
                aZ[r][0] = ffma2(ad, vza.x, aZ[r][0]);
                aZ[r][1] = ffma2(ad, vza.y, aZ[r][1]);
                aZ[r][2] = ffma2(ad, vzb.x, aZ[r][2]);
                aZ[r][3] = ffma2(ad, vzb.y, aZ[r][3]);
                aR[r][0] = ffma2(ad, vra.x, aR[r][0]);
                aR[r][1] = ffma2(ad, vra.y, aR[r][1]);
                aR[r][2] = ffma2(ad, vrb.x, aR[r][2]);
                aR[r][3] = ffma2(ad, vrb.y, aR[r][3]);
            }
        }
    }
}

__device__ __forceinline__ void bias4(u64 acc[4][4], const float* bb, int c0) {
    u64 t0 = pk2(bb[c0],      bb[c0 + 1]);
    u64 t1 = pk2(bb[c0 + 2],  bb[c0 + 3]);
    u64 t2 = pk2(bb[c0 + 32], bb[c0 + 33]);
    u64 t3 = pk2(bb[c0 + 34], bb[c0 + 35]);
#pragma unroll
    for (int r = 0; r < 4; ++r) {
        acc[r][0] = t0; acc[r][1] = t1; acc[r][2] = t2; acc[r][3] = t3;
    }
}

__device__ __forceinline__ void zero4(u64 acc[4][4]) {
    u64 z = pk2(0.0f, 0.0f);
#pragma unroll
    for (int r = 0; r < 4; ++r) {
        acc[r][0] = z; acc[r][1] = z; acc[r][2] = z; acc[r][3] = z;
    }
}

__device__ __forceinline__ void unpack8(float o[8], const u64 acc[4]) {
    upk2(o[0], o[1], acc[0]); upk2(o[2], o[3], acc[1]);
    upk2(o[4], o[5], acc[2]); upk2(o[6], o[7], acc[3]);
}

__global__ __launch_bounds__(256, 1)
void mgcgru_scan(const float* __restrict__ x,
                 const float* __restrict__ dyn,
                 const float* __restrict__ W1, const float* __restrict__ b1,
                 const float* __restrict__ W2, const float* __restrict__ b2,
                 const float* __restrict__ Wz, const float* __restrict__ bz,
                 const float* __restrict__ Wr, const float* __restrict__ br,
                 const float* __restrict__ Ww, const float* __restrict__ bw)
{
    extern __shared__ float sm[];
    float* sW2  = sm + OFF_W2;
    float* sWz  = sm + OFF_WZ;
    float* sWr  = sm + OFF_WR;
    float* sWw  = sm + OFF_WW;
    float* sW1  = sm + OFF_W1;
    float* sh   = sm + OFF_H;
    float* swk  = sm + OFF_WK;
    float* sdyn = sm + OFF_DYN;
    float* sxt  = sm + OFF_XT;
    float* sagg = sm + OFF_AGG;
    float* sb1  = sm + OFF_B1;
    float* sb2  = sm + OFF_B2;
    float* sbz  = sm + OFF_BZ;
    float* sbr  = sm + OFF_BR;
    float* sbw  = sm + OFF_BW;

    const int tid = threadIdx.x;
    const int b   = blockIdx.x;

    // preload weights; zero-pad dyn to 112 rows x 104 cols
    for (int i = tid; i < NVP * DSTR; i += 256) {
        int u = i / DSTR, v = i - u * DSTR;
        sdyn[i] = (u < NV && v < NV) ? dyn[u * NV + v] : 0.0f;
    }
    for (int i = tid; i < NC * ND; i += 256) sW1[i] = W1[i];
    for (int i = tid; i < ND * ND; i += 256) sW2[i] = W2[i];
    for (int i = tid; i < 132 * ND; i += 256) {
        sWz[i] = Wz[i]; sWr[i] = Wr[i]; sWw[i] = Ww[i];
    }
    if (tid < ND) {
        sb1[tid] = b1[tid]; sb2[tid] = b2[tid];
        sbz[tid] = bz[tid]; sbr[tid] = br[tid]; sbw[tid] = bw[tid];
    }
    // zero full padded state incl. stride pads (must be 0 and stay 0)
    for (int i = tid; i < NVP * HSTR; i += 256) { sh[i] = 0.0f; swk[i] = 0.0f; }
    for (int i = tid; i < NVP * NC; i += 256) { sxt[i] = 0.0f; sagg[i] = 0.0f; }

    // ownership: 7 active warps; warp w covers rows [w*16, w*16+16).
    // lane: lc = lane&7 -> col panels {4lc..4lc+3, 32+4lc..32+4lc+3};
    //       lr = lane>>3 -> row = w*16 + r*4 + lr (r=0..3).
    const int w    = tid >> 5;
    const int lane = tid & 31;
    const int lr   = lane >> 3;        // 0..3
    const int lc   = lane & 7;         // 0..7
    const int c0   = lc * 4;
    const int rowbase = w * 16 + lr;   // + r*4
    const bool active = (w < 7);

    __syncthreads();

    for (int t = 0; t < NT; ++t) {
        // load x_t slice (101 x 4)
        if (tid < NV) {
            float4 xv = *reinterpret_cast<const float4*>(
                x + (((size_t)b * NV + tid) * NT + t) * NC);
            *reinterpret_cast<float4*>(sxt + tid * 4) = xv;
        }
        __syncthreads();

        // stage1: agg[u][c] = sum_v dyn[u][v] * xt[v][c]  (tiny)
        // NOTE: grid-stride loop — NV*NC = 404 > 256 threads (R14 bug was an if)
        for (int i = tid; i < NV * NC; i += 256) {
            int uu = i >> 2, c = i & 3;
            const float* dr = sdyn + uu * DSTR;
            float s = 0.0f;
#pragma unroll 4
            for (int v = 0; v < NV; ++v) s = fmaf(dr[v], sxt[v * 4 + c], s);
            sagg[i] = s;
        }
        __syncthreads();

        // stage2: f1 = tanh(agg @ W1 + b1) -> swk
        if (active) {
            u64 acc[4][4];
            bias4(acc, sb1, c0);
            gemmT(acc, sagg, 4, rowbase, sW1, 64, 4, c0);
#pragma unroll
            for (int r = 0; r < 4; ++r) {
                int row = rowbase + r * 4;
                if (row < NV) {
                    float o[8]; unpack8(o, acc[r]);
                    *reinterpret_cast<float4*>(swk + row * HSTR + c0) =
                        make_float4(tanh_fast(o[0]), tanh_fast(o[1]), tanh_fast(o[2]), tanh_fast(o[3]));
                    *reinterpret_cast<float4*>(swk + row * HSTR + c0 + 32) =
                        make_float4(tanh_fast(o[4]), tanh_fast(o[5]), tanh_fast(o[6]), tanh_fast(o[7]));
                }
            }
        }
        __syncthreads();

        // stage3: agg2 = dyn @ f1 (K=104; swk is the weight, stride HSTR)
        {
            u64 acc[4][4];
            if (active) {
                zero4(acc);
                gemmT(acc, sdyn, DSTR, rowbase, swk, HSTR, 104, c0);
            }
            __syncthreads();   // all reads of f1 complete
            if (active) {
#pragma unroll
                for (int r = 0; r < 4; ++r) {
                    int row = rowbase + r * 4;
                    if (row < NV) {
                        float o[8]; unpack8(o, acc[r]);
                        *reinterpret_cast<float4*>(swk + row * HSTR + c0) =
                            make_float4(o[0], o[1], o[2], o[3]);
                        *reinterpret_cast<float4*>(swk + row * HSTR + c0 + 32) =
                            make_float4(o[4], o[5], o[6], o[7]);
                    }
                }
            }
        }
        __syncthreads();

        // stage4: f = tanh(agg2 @ W2 + b2) -> swk (reg-staged overwrite)
        {
            u64 acc[4][4];
            if (active) {
                bias4(acc, sb2, c0);
                gemmT(acc, swk, HSTR, rowbase, sW2, 64, 64, c0);
            }
            __syncthreads();   // all reads of agg2 complete
            if (active) {
#pragma unroll
                for (int r = 0; r < 4; ++r) {
                    int row = rowbase + r * 4;
                    if (row < NV) {
                        float o[8]; unpack8(o, acc[r]);
                        *reinterpret_cast<float4*>(swk + row * HSTR + c0) =
                            make_float4(tanh_fast(o[0]), tanh_fast(o[1]), tanh_fast(o[2]), tanh_fast(o[3]));
                        *reinterpret_cast<float4*>(swk + row * HSTR + c0 + 32) =
                            make_float4(tanh_fast(o[4]), tanh_fast(o[5]), tanh_fast(o[6]), tanh_fast(o[7]));
                    }
                }
            }
        }
        __syncthreads();

        // gates (fused). cat = [xt(4) | f(64) | h(64)]
        float zf[4][8];
        float rh[4][8];
        u64 wacc[4][4];
        if (active) {
            u64 zacc[4][4], racc[4][4];
            bias4(zacc, sbz, c0);
            bias4(racc, sbr, c0);
            bias4(wacc, sbw, c0);
            gemmT3(zacc, racc, wacc, sxt, 4, rowbase, sWz, sWr, sWw, 4, c0);
            gemmT3(zacc, racc, wacc, swk, HSTR, rowbase,
                   sWz + 4 * 64, sWr + 4 * 64, sWw + 4 * 64, 64, c0);
            gemmT2(zacc, racc, sh, HSTR, rowbase,
                   sWz + 68 * 64, sWr + 68 * 64, 64, c0);
#pragma unroll
            for (int r = 0; r < 4; ++r) {
                unpack8(zf[r], zacc[r]);
#pragma unroll
                for (int j = 0; j < 8; ++j) zf[r][j] = sigm(zf[r][j]);
            }
#pragma unroll
            for (int r = 0; r < 4; ++r) {
                int row = rowbase + r * 4;
                unpack8(rh[r], racc[r]);
                float4 h0 = *reinterpret_cast<const float4*>(sh + row * HSTR + c0);
                float4 h1 = *reinterpret_cast<const float4*>(sh + row * HSTR + c0 + 32);
                rh[r][0] = sigm(rh[r][0]) * h0.x;
                rh[r][1] = sigm(rh[r][1]) * h0.y;
                rh[r][2] = sigm(rh[r][2]) * h0.z;
                rh[r][3] = sigm(rh[r][3]) * h0.w;
                rh[r][4] = sigm(rh[r][4]) * h1.x;
                rh[r][5] = sigm(rh[r][5]) * h1.y;
                rh[r][6] = sigm(rh[r][6]) * h1.z;
                rh[r][7] = sigm(rh[r][7]) * h1.w;
            }
        }

        __syncthreads();   // all reads of f and h (by other lanes) complete
        // write r*h over swk (pad rows stay zero: guarded)
        if (active) {
#pragma unroll
            for (int r = 0; r < 4; ++r) {
                int row = rowbase + r * 4;
                if (row < NV) {
                    *reinterpret_cast<float4*>(swk + row * HSTR + c0) =
                        make_float4(rh[r][0], rh[r][1], rh[r][2], rh[r][3]);
                    *reinterpret_cast<float4*>(swk + row * HSTR + c0 + 32) =
                        make_float4(rh[r][4], rh[r][5], rh[r][6], rh[r][7]);
                }
            }
        }
        __syncthreads();

        // stage7: wpre += (r*h) @ Ww_h ; h = h + z*(tanh(wpre) - h)
        if (active) {
            gemmT(wacc, swk, HSTR, rowbase, sWw + 68 * 64, 64, 64, c0);
#pragma unroll
            for (int r = 0; r < 4; ++r) {
                int row = rowbase + r * 4;
                if (row < NV) {
                    float o[8]; unpack8(o, wacc[r]);
                    float* hp = sh + row * HSTR;
                    float4 h0 = *reinterpret_cast<const float4*>(hp + c0);
                    float4 h1 = *reinterpret_cast<const float4*>(hp + c0 + 32);
                    float n0 = h0.x + zf[r][0] * (tanh_fast(o[0]) - h0.x);
                    float n1 = h0.y + zf[r][1] * (tanh_fast(o[1]) - h0.y);
                    float n2 = h0.z + zf[r][2] * (tanh_fast(o[2]) - h0.z);
                    float n3 = h0.w + zf[r][3] * (tanh_fast(o[3]) - h0.w);
                    float n4 = h1.x + zf[r][4] * (tanh_fast(o[4]) - h1.x);
                    float n5 = h1.y + zf[r][5] * (tanh_fast(o[5]) - h1.y);
                    float n6 = h1.z + zf[r][6] * (tanh_fast(o[6]) - h1.z);
                    float n7 = h1.w + zf[r][7] * (tanh_fast(o[7]) - h1.w);
                    *reinterpret_cast<float4*>(hp + c0) = make_float4(n0, n1, n2, n3);
                    *reinterpret_cast<float4*>(hp + c0 + 32) = make_float4(n4, n5, n6, n7);
                }
            }
        }
        // top-of-loop barriers order h writes vs next reads
    }

    __syncthreads();
    for (int i = tid; i < NV * ND; i += 256) {
        int u = i >> 6, c = i & 63;
        g_h[(size_t)b * (NV * ND) + i] = sh[u * HSTR + c];
    }
}

// ---------------- FC1: g_y = relu(g_h @ Wf1 + bf1), M=8192 K=6464 N=128 ----
__global__ __launch_bounds__(256, 2)
void fc1_kernel(const float* __restrict__ Wf1, const float* __restrict__ bf1)
{
    __shared__ float sA[64 * 16];
    __shared__ float sB[16 * 128];
    const int tid = threadIdx.x;
    const int m0  = blockIdx.x * 64;
    const int tn  = tid & 31;   // 0..31 -> 4 cols each
    const int tm  = tid >> 5;   // 0..7  -> 8 rows each

    float acc[8][4];
#pragma unroll
    for (int i = 0; i < 8; ++i)
#pragma unroll
        for (int j = 0; j < 4; ++j) acc[i][j] = 0.0f;

    const int ai = tid >> 2, ak = (tid & 3) * 4;
    const int bk = tid >> 4, bn = (tid & 15) * 8;

    for (int k0 = 0; k0 < NV * ND; k0 += 16) {
        *reinterpret_cast<float4*>(&sA[ai * 16 + ak]) =
            *reinterpret_cast<const float4*>(&g_h[(size_t)(m0 + ai) * (NV * ND) + k0 + ak]);
        *reinterpret_cast<float4*>(&sB[bk * 128 + bn]) =
            *reinterpret_cast<const float4*>(&Wf1[(size_t)(k0 + bk) * 128 + bn]);
        *reinterpret_cast<float4*>(&sB[bk * 128 + bn + 4]) =
            *reinterpret_cast<const float4*>(&Wf1[(size_t)(k0 + bk) * 128 + bn + 4]);
        __syncthreads();
#pragma unroll
        for (int kk = 0; kk < 16; ++kk) {
            float bv[4];
            *reinterpret_cast<float4*>(bv) =
                *reinterpret_cast<const float4*>(&sB[kk * 128 + tn * 4]);
#pragma unroll
            for (int i = 0; i < 8; ++i) {
                float av = sA[(tm * 8 + i) * 16 + kk];
                acc[i][0] = fmaf(av, bv[0], acc[i][0]);
                acc[i][1] = fmaf(av, bv[1], acc[i][1]);
                acc[i][2] = fmaf(av, bv[2], acc[i][2]);
                acc[i][3] = fmaf(av, bv[3], acc[i][3]);
            }
        }
        __syncthreads();
    }
#pragma unroll
    for (int i = 0; i < 8; ++i) {
        int m = m0 + tm * 8 + i;
#pragma unroll
        for (int j = 0; j < 4; ++j) {
            int n = tn * 4 + j;
            g_y[(size_t)m * 128 + n] = fmaxf(acc[i][j] + bf1[n], 0.0f);
        }
    }
}

// ---------------- head: out = softmax(g_y @ Wf2 + bf2) ----------------
__global__ __launch_bounds__(128)
void head_kernel(const float* __restrict__ Wf2, const float* __restrict__ bf2,
                 float* __restrict__ out)
{
    const int b = blockIdx.x, tid = threadIdx.x;
    __shared__ float sy[128];
    __shared__ float red[128];

    sy[tid] = g_y[(size_t)b * 128 + tid];
    __syncthreads();

    float logit = -3.0e38f;
    if (tid < NV) {
        float s = bf2[tid];
#pragma unroll 4
        for (int k = 0; k < 128; ++k) s = fmaf(sy[k], Wf2[k * NV + tid], s);
        logit = s;
    }
    red[tid] = logit;
    __syncthreads();
#pragma unroll
    for (int off = 64; off > 0; off >>= 1) {
        if (tid < off) red[tid] = fmaxf(red[tid], red[tid + off]);
        __syncthreads();
    }
    float m = red[0];
    __syncthreads();
    float e = (tid < NV) ? expf(logit - m) : 0.0f;
    red[tid] = e;
    __syncthreads();
#pragma unroll
    for (int off = 64; off > 0; off >>= 1) {
        if (tid < off) red[tid] += red[tid + off];
        __syncthreads();
    }
    float s = red[0];
    if (tid < NV) out[(size_t)b * NV + tid] = e / s;
}

extern "C" void kernel_launch(void* const* d_in, const int* in_sizes, int n_in,
                              void* d_out, int out_size)
{
    (void)in_sizes; (void)n_in; (void)out_size;
    const float* x   = (const float*)d_in[0];
    const float* dyn = (const float*)d_in[1];
    const float* W1  = (const float*)d_in[2];
    const float* b1  = (const float*)d_in[3];
    const float* W2  = (const float*)d_in[4];
    const float* b2  = (const float*)d_in[5];
    const float* Wz  = (const float*)d_in[6];
    const float* bz  = (const float*)d_in[7];
    const float* Wr  = (const float*)d_in[8];
    const float* br  = (const float*)d_in[9];
    const float* Ww  = (const float*)d_in[10];
    const float* bw  = (const float*)d_in[11];
    const float* Wf1 = (const float*)d_in[12];
    const float* bf1 = (const float*)d_in[13];
    const float* Wf2 = (const float*)d_in[14];
    const float* bf2 = (const float*)d_in[15];
    float* out = (float*)d_out;

    cudaFuncSetAttribute(mgcgru_scan, cudaFuncAttributeMaxDynamicSharedMemorySize, SMEM_BYTES);
    mgcgru_scan<<<NB, 256, SMEM_BYTES>>>(x, dyn, W1, b1, W2, b2, Wz, bz, Wr, br, Ww, bw);
    fc1_kernel<<<NB / 64, 256>>>(Wf1, bf1);
    head_kernel<<<NB, 128>>>(Wf2, bf2, out);
}